// round 13
// baseline (speedup 1.0000x reference)
#include <cuda_runtime.h>
#include <cuda_fp16.h>
#include <cstdint>
#include <cstring>

// ---------------------------------------------------------------------------
// SyntaxGCN: GCNConv(512->256) + relu + global_mean_pool + linear(256->1) + sigmoid
// R13: convert_x eliminated — GEMM A-loader reads fp32 x directly (LDG.128),
//      scales by dinv, converts to fp16 in registers, STS to staging.
//      Removes 82MB of convert round-trip traffic + one kernel launch.
//      Datapath otherwise identical to R12 (fp16 single-pass, fp16 hs).
// ---------------------------------------------------------------------------

constexpr int N_NODES  = 20000;
constexpr int N_EDGES  = 320000;
constexpr int IN_DIM   = 512;
constexpr int HID      = 256;
constexpr int N_GRAPHS = 256;
constexpr int CSR_CAP  = 128;

constexpr int TILE_M = 128;
constexpr int TILE_N = 128;
constexpr int TK     = 32;
constexpr int NCHUNK = IN_DIM / TK;        // 16
constexpr int SSTR   = 40;                 // smem row stride in f16 (80B, LDSM conflict-free)
constexpr int MAT    = TILE_M * SSTR;      // 5120
constexpr int OFF_B  = MAT;
constexpr int STAGE  = 2 * MAT;            // 10240 f16 = 20.5KB
constexpr int SMEM_BYTES = 2 * STAGE * (int)sizeof(__half);  // 40960

// Scratch (device globals)
__device__ uint2  g_hsh[N_NODES * HID / 4];      // hs in fp16 (half2 pairs)
__device__ float  g_dinv[N_NODES];
__device__ int    g_cnt[N_NODES];
__device__ int    g_csr[N_NODES * CSR_CAP];
__device__ float4 g_pooled[N_GRAPHS * HID / 4];
__device__ float  g_counts[N_GRAPHS];
__device__ uint4  g_wt[HID * IN_DIM / 8];        // fp16 W, transposed [n][k]

// ---------------- helpers ---------------------------------------------------
__device__ __forceinline__ void red_add_v4(float4* addr, float4 v) {
    asm volatile("red.global.add.v4.f32 [%0], {%1,%2,%3,%4};"
                 :: "l"(addr), "f"(v.x), "f"(v.y), "f"(v.z), "f"(v.w)
                 : "memory");
}

__device__ __forceinline__ uint32_t smem_u32(const void* p) {
    uint32_t a;
    asm("{ .reg .u64 t; cvta.to.shared.u64 t, %1; cvt.u32.u64 %0, t; }" : "=r"(a) : "l"(p));
    return a;
}

__device__ __forceinline__ void cp16(void* dst_smem, const void* src) {
    asm volatile("cp.async.ca.shared.global [%0], [%1], 16;"
                 :: "r"(smem_u32(dst_smem)), "l"(src) : "memory");
}

__device__ __forceinline__ void ldsm_x4(uint32_t* r, uint32_t addr) {
    asm volatile("ldmatrix.sync.aligned.m8n8.x4.shared.b16 {%0,%1,%2,%3}, [%4];"
                 : "=r"(r[0]), "=r"(r[1]), "=r"(r[2]), "=r"(r[3]) : "r"(addr));
}

__device__ __forceinline__ void mma_f16(float* c, const uint32_t* a,
                                        uint32_t b0, uint32_t b1) {
    asm volatile(
        "mma.sync.aligned.m16n8k16.row.col.f32.f16.f16.f32 "
        "{%0,%1,%2,%3}, {%4,%5,%6,%7}, {%8,%9}, {%0,%1,%2,%3};"
        : "+f"(c[0]), "+f"(c[1]), "+f"(c[2]), "+f"(c[3])
        : "r"(a[0]), "r"(a[1]), "r"(a[2]), "r"(a[3]), "r"(b0), "r"(b1));
}

__device__ __forceinline__ uint32_t f2h2(float a, float b) {
    __half2 h = __halves2half2(__float2half_rn(a), __float2half_rn(b));
    uint32_t u; memcpy(&u, &h, 4);
    return u;
}

// --- init -------------------------------------------------------------------
__global__ void init_kernel() {
    int i = blockIdx.x * blockDim.x + threadIdx.x;
    if (i < N_GRAPHS * HID / 4) g_pooled[i] = make_float4(0.f, 0.f, 0.f, 0.f);
    if (i < N_GRAPHS)           g_counts[i] = 0.f;
    if (i < N_NODES)            g_cnt[i] = 0;
}

__global__ void edge_bin_kernel(const int* __restrict__ ei) {
    int e = blockIdx.x * blockDim.x + threadIdx.x;
    if (e >= N_EDGES) return;
    int src = __ldg(&ei[e]);
    int dst = __ldg(&ei[N_EDGES + e]);
    int pos = atomicAdd(&g_cnt[dst], 1);
    if (pos < CSR_CAP) g_csr[dst * CSR_CAP + pos] = src;
}

__global__ void dinv_kernel() {
    int n = blockIdx.x * blockDim.x + threadIdx.x;
    if (n < N_NODES) g_dinv[n] = rsqrtf((float)(g_cnt[n] + 1));
}

// --- preconvert W -> transposed fp16 [n][k] ---------------------------------
__global__ __launch_bounds__(256) void convert_w_kernel(const float4* __restrict__ W4) {
    int i = blockIdx.x * blockDim.x + threadIdx.x;
    if (i >= IN_DIM * HID / 4) return;
    int k  = i >> 6;
    int n4 = i & 63;
    float4 v = W4[i];
    float f[4] = {v.x, v.y, v.z, v.w};
    __half* wt = (__half*)g_wt;
    #pragma unroll
    for (int j = 0; j < 4; j++)
        wt[(size_t)(n4 * 4 + j) * IN_DIM + k] = __float2half_rn(f[j]);
}

// --- tensor-core GEMM: hs = fp16( (x*dinv) @ W ) ----------------------------
// A converted in-loader from fp32 (register double-buffer); B via cp.async.
// 256 threads, 8 warps (4m x 2n), warp tile 32x64, 2-stage, ldmatrix.
__global__ __launch_bounds__(256, 2) void gemm_mma_kernel(const float* __restrict__ X) {
    extern __shared__ __half sm[];
    const uint32_t smaddr = smem_u32(sm);

    const int tid  = threadIdx.x;
    const int lane = tid & 31;
    const int wid  = tid >> 5;
    const int warp_m = wid & 3;
    const int warp_n = wid >> 2;
    const int quad  = lane >> 2;
    const int tig   = lane & 3;

    const int m0 = blockIdx.y * TILE_M;
    const int n0 = blockIdx.x * TILE_N;

    const __half* wt = (const __half*)g_wt;

    float acc[2][8][4];
    #pragma unroll
    for (int i = 0; i < 2; i++)
        #pragma unroll
        for (int j = 0; j < 8; j++)
            #pragma unroll
            for (int c = 0; c < 4; c++) acc[i][j][c] = 0.f;

    // ldmatrix per-lane address components (in f16 elements)
    const int a_row = lane & 15;
    const int a_k   = (lane & 16) ? 8 : 0;
    const int a_base = (warp_m * 32 + a_row) * SSTR + a_k;
    const int b_row = ((lane >> 4) & 1) * 8 + (lane & 7);
    const int b_k   = (lane & 8) ? 8 : 0;
    const int b_base = (warp_n * 64 + b_row) * SSTR + b_k;

    // ---- A loader mapping: 2 threads per row, 16 fp32 each ----------------
    const int l_row  = tid >> 1;           // 0..127
    const int l_half = tid & 1;            // k offset 0 / 16
    int gr = m0 + l_row; if (gr >= N_NODES) gr = 0;
    const float* xrow = X + (size_t)gr * IN_DIM + l_half * 16;
    const float  drow = __ldg(&g_dinv[gr]);        // row fixed for this thread
    const int a_doff = l_row * SSTR + l_half * 16; // f16 elements

    float af[16];                          // staged fp32 for next chunk
    auto ldgA = [&](int chunk) {
        const float* p = xrow + chunk * TK;
        #pragma unroll
        for (int q = 0; q < 4; q++)
            *(float4*)&af[q * 4] = __ldg((const float4*)(p + q * 4));
    };
    auto stsA = [&](int s) {
        uint4 h0, h1;
        h0.x = f2h2(af[0] * drow,  af[1] * drow);
        h0.y = f2h2(af[2] * drow,  af[3] * drow);
        h0.z = f2h2(af[4] * drow,  af[5] * drow);
        h0.w = f2h2(af[6] * drow,  af[7] * drow);
        h1.x = f2h2(af[8] * drow,  af[9] * drow);
        h1.y = f2h2(af[10] * drow, af[11] * drow);
        h1.z = f2h2(af[12] * drow, af[13] * drow);
        h1.w = f2h2(af[14] * drow, af[15] * drow);
        __half* d = sm + s * STAGE + a_doff;
        *(uint4*)d       = h0;
        *(uint4*)(d + 8) = h1;
    };
    // B loader: 512 x 16B cp.async per stage (2 per thread)
    auto cpB = [&](int s, int chunk) {
        const int k0 = chunk * TK;
        __half* st = sm + s * STAGE + OFF_B;
        #pragma unroll
        for (int r = 0; r < 2; r++) {
            int idx = tid + 256 * r;
            int row = idx >> 2;
            int c   = idx & 3;
            cp16(st + row * SSTR + c * 8,
                 wt + (size_t)(n0 + row) * IN_DIM + k0 + c * 8);
        }
    };

    // prologue: stage 0 fully populated
    ldgA(0); stsA(0);
    cpB(0, 0);
    asm volatile("cp.async.commit_group;" ::: "memory");

    for (int chunk = 0; chunk < NCHUNK; chunk++) {
        const bool more = chunk + 1 < NCHUNK;
        if (more) {
            ldgA(chunk + 1);                       // LDGs issue early
            cpB((chunk + 1) & 1, chunk + 1);
        }
        asm volatile("cp.async.commit_group;" ::: "memory");
        asm volatile("cp.async.wait_group 1;" ::: "memory");
        __syncthreads();                           // stage[chunk&1] ready

        const uint32_t stg = smaddr + (uint32_t)(chunk & 1) * (STAGE * 2);

        #pragma unroll
        for (int ks = 0; ks < 2; ks++) {
            const int kb = ks * 16;
            uint32_t a0[4], a1[4];
            uint32_t aa = stg + (uint32_t)(a_base + kb) * 2;
            ldsm_x4(a0, aa);
            ldsm_x4(a1, aa + 16 * SSTR * 2);
            #pragma unroll
            for (int p = 0; p < 4; p++) {
                uint32_t ba = stg + (uint32_t)(b_base + p * 16 * SSTR + kb) * 2;
                uint32_t bh[4];
                ldsm_x4(bh, ba + OFF_B * 2);
                mma_f16(acc[0][2 * p],     a0, bh[0], bh[1]);
                mma_f16(acc[1][2 * p],     a1, bh[0], bh[1]);
                mma_f16(acc[0][2 * p + 1], a0, bh[2], bh[3]);
                mma_f16(acc[1][2 * p + 1], a1, bh[2], bh[3]);
            }
        }
        if (more) stsA((chunk + 1) & 1);           // into idle stage
        __syncthreads();
    }

    // ---- epilogue: store hs as fp16 (half2 per acc pair) ------------------
    __half* hsh = (__half*)g_hsh;
    #pragma unroll
    for (int i = 0; i < 2; i++) {
        const int r0 = m0 + warp_m * 32 + i * 16 + quad;
        const int r1 = r0 + 8;
        const bool v0 = r0 < N_NODES;
        const bool v1 = r1 < N_NODES;
        #pragma unroll
        for (int j = 0; j < 8; j++) {
            const int col = n0 + warp_n * 64 + j * 8 + tig * 2;
            if (v0)
                *(uint32_t*)(hsh + (size_t)r0 * HID + col) = f2h2(acc[i][j][0], acc[i][j][1]);
            if (v1)
                *(uint32_t*)(hsh + (size_t)r1 * HID + col) = f2h2(acc[i][j][2], acc[i][j][3]);
        }
    }
}

// --- gather + relu + pool: one node per 64 threads, fp16 rows ---------------
__global__ __launch_bounds__(256) void gather_pool_kernel(
    const int* __restrict__ batch, const float* __restrict__ b)
{
    int t = blockIdx.x * blockDim.x + threadIdx.x;
    int n = t >> 6;
    int lane = t & 63;
    if (n >= N_NODES) return;

    int cnt = g_cnt[n];
    if (cnt > CSR_CAP) cnt = CSR_CAP;
    const int* lst = g_csr + n * CSR_CAP;

    auto addrow = [&](float4& a, uint2 raw) {
        __half2 p0, p1;
        memcpy(&p0, &raw.x, 4);
        memcpy(&p1, &raw.y, 4);
        float2 f0 = __half22float2(p0);
        float2 f1 = __half22float2(p1);
        a.x += f0.x; a.y += f0.y; a.z += f1.x; a.w += f1.y;
    };

    float4 a = make_float4(0.f, 0.f, 0.f, 0.f);
    addrow(a, __ldg(&g_hsh[(size_t)n * 64 + lane]));   // self loop

    int i = 0;
    for (; i + 8 <= cnt; i += 8) {
        int s[8];
        #pragma unroll
        for (int q = 0; q < 8; q++) s[q] = __ldg(&lst[i + q]);
        uint2 v[8];
        #pragma unroll
        for (int q = 0; q < 8; q++) v[q] = __ldg(&g_hsh[(size_t)s[q] * 64 + lane]);
        #pragma unroll
        for (int q = 0; q < 8; q++) addrow(a, v[q]);
    }
    for (; i < cnt; i++) {
        int s = __ldg(&lst[i]);
        addrow(a, __ldg(&g_hsh[(size_t)s * 64 + lane]));
    }

    float d = g_dinv[n];
    float4 bb = __ldg((const float4*)b + lane);
    float4 v;
    v.x = fmaxf(fmaf(a.x, d, bb.x), 0.f);
    v.y = fmaxf(fmaf(a.y, d, bb.y), 0.f);
    v.z = fmaxf(fmaf(a.z, d, bb.z), 0.f);
    v.w = fmaxf(fmaf(a.w, d, bb.w), 0.f);

    int g = __ldg(&batch[n]);
    red_add_v4(&g_pooled[(size_t)g * 64 + lane], v);
    if (lane == 0) atomicAdd(&g_counts[g], 1.f);
}

// --- head --------------------------------------------------------------------
__global__ void head_kernel(
    const float* __restrict__ lin_w, const float* __restrict__ lin_b,
    float* __restrict__ out)
{
    __shared__ float red[256];
    int g = blockIdx.x;
    int t = threadIdx.x;
    const float* pooled = (const float*)g_pooled;
    red[t] = pooled[g * HID + t] * __ldg(&lin_w[t]);
    __syncthreads();
    #pragma unroll
    for (int s = 128; s > 0; s >>= 1) {
        if (t < s) red[t] += red[t + s];
        __syncthreads();
    }
    if (t == 0) {
        float cnt = fmaxf(g_counts[g], 1.f);
        float z = red[0] / cnt + __ldg(&lin_b[0]);
        out[g] = 1.f / (1.f + expf(-z));
    }
}

// ---------------------------------------------------------------------------
extern "C" void kernel_launch(void* const* d_in, const int* in_sizes, int n_in,
                              void* d_out, int out_size) {
    const float* x     = (const float*)d_in[0];
    const int*   ei    = (const int*)d_in[1];
    const int*   batch = (const int*)d_in[2];
    const float* W     = (const float*)d_in[3];
    const float* b     = (const float*)d_in[4];
    const float* lin_w = (const float*)d_in[5];
    const float* lin_b = (const float*)d_in[6];
    float*       out   = (float*)d_out;

    static bool attr_set = false;
    if (!attr_set) {
        cudaFuncSetAttribute(gemm_mma_kernel,
                             cudaFuncAttributeMaxDynamicSharedMemorySize, SMEM_BYTES);
        attr_set = true;
    }

    init_kernel<<<(N_GRAPHS * HID + 255) / 256, 256>>>();
    edge_bin_kernel<<<(N_EDGES + 255) / 256, 256>>>(ei);
    dinv_kernel<<<(N_NODES + 255) / 256, 256>>>();
    convert_w_kernel<<<(IN_DIM * HID / 4 + 255) / 256, 256>>>((const float4*)W);
    gemm_mma_kernel<<<dim3(HID / TILE_N, (N_NODES + TILE_M - 1) / TILE_M),
                      256, SMEM_BYTES>>>(x);
    gather_pool_kernel<<<(N_NODES * 64 + 255) / 256, 256>>>(batch, b);
    head_kernel<<<N_GRAPHS, 256>>>(lin_w, lin_b, out);
}

// round 14
// speedup vs baseline: 1.0927x; 1.0927x over previous
#include <cuda_runtime.h>
#include <cuda_fp16.h>
#include <cstdint>
#include <cstring>

// ---------------------------------------------------------------------------
// SyntaxGCN: GCNConv(512->256) + relu + global_mean_pool + linear(256->1) + sigmoid
// R14: R12 datapath (fp16 single-pass GEMM at the mma.sync issue ceiling,
//      fp16 hs, CSR gather+pool). Changes:
//      - W kept [k][n]; GEMM B loads via ldmatrix.trans (convert_w -> ~1us)
//      - convert_x with 4x MLP (front-batched independent loads)
// ---------------------------------------------------------------------------

constexpr int N_NODES  = 20000;
constexpr int N_EDGES  = 320000;
constexpr int IN_DIM   = 512;
constexpr int HID      = 256;
constexpr int N_GRAPHS = 256;
constexpr int CSR_CAP  = 128;

constexpr int TILE_M = 128;
constexpr int TILE_N = 128;
constexpr int TK     = 32;
constexpr int NCHUNK = IN_DIM / TK;        // 16
constexpr int SSTR   = 40;                 // A smem row stride (f16); LDSM conflict-free
constexpr int SSTRB  = 136;                // B smem row stride (f16); 272B -> distinct banks
constexpr int MAT    = TILE_M * SSTR;      // 5120
constexpr int OFF_B  = MAT;
constexpr int B_SZ   = TK * SSTRB;         // 4352
constexpr int STAGE  = MAT + B_SZ;         // 9472 f16
constexpr int SMEM_BYTES = 2 * STAGE * (int)sizeof(__half);  // 37888

// Scratch (device globals)
__device__ uint2  g_hsh[N_NODES * HID / 4];      // hs in fp16 (half2 pairs)
__device__ float  g_dinv[N_NODES];
__device__ int    g_cnt[N_NODES];
__device__ int    g_csr[N_NODES * CSR_CAP];
__device__ float4 g_pooled[N_GRAPHS * HID / 4];
__device__ float  g_counts[N_GRAPHS];
__device__ uint4  g_xh[N_NODES * IN_DIM / 8];    // fp16 x, pre-scaled by dinv
__device__ uint4  g_wt[IN_DIM * HID / 8];        // fp16 W, SAME layout [k][n]

// ---------------- helpers ---------------------------------------------------
__device__ __forceinline__ void red_add_v4(float4* addr, float4 v) {
    asm volatile("red.global.add.v4.f32 [%0], {%1,%2,%3,%4};"
                 :: "l"(addr), "f"(v.x), "f"(v.y), "f"(v.z), "f"(v.w)
                 : "memory");
}

__device__ __forceinline__ uint32_t smem_u32(const void* p) {
    uint32_t a;
    asm("{ .reg .u64 t; cvta.to.shared.u64 t, %1; cvt.u32.u64 %0, t; }" : "=r"(a) : "l"(p));
    return a;
}

__device__ __forceinline__ void cp16(void* dst_smem, const void* src) {
    asm volatile("cp.async.ca.shared.global [%0], [%1], 16;"
                 :: "r"(smem_u32(dst_smem)), "l"(src) : "memory");
}

__device__ __forceinline__ void ldsm_x4(uint32_t* r, uint32_t addr) {
    asm volatile("ldmatrix.sync.aligned.m8n8.x4.shared.b16 {%0,%1,%2,%3}, [%4];"
                 : "=r"(r[0]), "=r"(r[1]), "=r"(r[2]), "=r"(r[3]) : "r"(addr));
}

__device__ __forceinline__ void ldsm_x4_trans(uint32_t* r, uint32_t addr) {
    asm volatile("ldmatrix.sync.aligned.m8n8.x4.trans.shared.b16 {%0,%1,%2,%3}, [%4];"
                 : "=r"(r[0]), "=r"(r[1]), "=r"(r[2]), "=r"(r[3]) : "r"(addr));
}

__device__ __forceinline__ void mma_f16(float* c, const uint32_t* a,
                                        uint32_t b0, uint32_t b1) {
    asm volatile(
        "mma.sync.aligned.m16n8k16.row.col.f32.f16.f16.f32 "
        "{%0,%1,%2,%3}, {%4,%5,%6,%7}, {%8,%9}, {%0,%1,%2,%3};"
        : "+f"(c[0]), "+f"(c[1]), "+f"(c[2]), "+f"(c[3])
        : "r"(a[0]), "r"(a[1]), "r"(a[2]), "r"(a[3]), "r"(b0), "r"(b1));
}

__device__ __forceinline__ uint32_t f2h2(float a, float b) {
    __half2 h = __halves2half2(__float2half_rn(a), __float2half_rn(b));
    uint32_t u; memcpy(&u, &h, 4);
    return u;
}

// --- init -------------------------------------------------------------------
__global__ void init_kernel() {
    int i = blockIdx.x * blockDim.x + threadIdx.x;
    if (i < N_GRAPHS * HID / 4) g_pooled[i] = make_float4(0.f, 0.f, 0.f, 0.f);
    if (i < N_GRAPHS)           g_counts[i] = 0.f;
    if (i < N_NODES)            g_cnt[i] = 0;
}

__global__ void edge_bin_kernel(const int* __restrict__ ei) {
    int e = blockIdx.x * blockDim.x + threadIdx.x;
    if (e >= N_EDGES) return;
    int src = __ldg(&ei[e]);
    int dst = __ldg(&ei[N_EDGES + e]);
    int pos = atomicAdd(&g_cnt[dst], 1);
    if (pos < CSR_CAP) g_csr[dst * CSR_CAP + pos] = src;
}

__global__ void dinv_kernel() {
    int n = blockIdx.x * blockDim.x + threadIdx.x;
    if (n < N_NODES) g_dinv[n] = rsqrtf((float)(g_cnt[n] + 1));
}

// --- preconvert xs = fp16(x*dinv), 4 independent float4 per thread ----------
__global__ __launch_bounds__(256) void convert_x_kernel(const float4* __restrict__ X4) {
    constexpr int TOT = N_NODES * IN_DIM / 4;       // 2,560,000 float4
    int base = blockIdx.x * 1024 + threadIdx.x;
    float4 v[4];
    int idx[4];
    #pragma unroll
    for (int q = 0; q < 4; q++) {
        idx[q] = base + 256 * q;
        if (idx[q] < TOT) v[q] = __ldg(&X4[idx[q]]);
    }
    #pragma unroll
    for (int q = 0; q < 4; q++) {
        if (idx[q] < TOT) {
            float d = __ldg(&g_dinv[idx[q] >> 7]);  // 128 float4 per row
            uint2 o;
            o.x = f2h2(v[q].x * d, v[q].y * d);
            o.y = f2h2(v[q].z * d, v[q].w * d);
            ((uint2*)g_xh)[idx[q]] = o;
        }
    }
}

// --- preconvert W -> fp16 same layout [k][n] (pure coalesced cast) ----------
__global__ __launch_bounds__(256) void convert_w_kernel(const float4* __restrict__ W4) {
    int i = blockIdx.x * blockDim.x + threadIdx.x;
    if (i >= IN_DIM * HID / 4) return;
    float4 v = W4[i];
    uint2 o;
    o.x = f2h2(v.x, v.y);
    o.y = f2h2(v.z, v.w);
    ((uint2*)g_wt)[i] = o;
}

// --- tensor-core GEMM: hs = fp16(xs @ W) ------------------------------------
// 256 threads, 8 warps (4m x 2n), warp tile 32x64, 2-stage cp.async.
// A: ldmatrix (row-major, [m][k] smem).  B: ldmatrix.trans ([k][n] smem).
__global__ __launch_bounds__(256, 2) void gemm_mma_kernel() {
    extern __shared__ __half sm[];
    const uint32_t smaddr = smem_u32(sm);

    const int tid  = threadIdx.x;
    const int lane = tid & 31;
    const int wid  = tid >> 5;
    const int warp_m = wid & 3;
    const int warp_n = wid >> 2;
    const int quad  = lane >> 2;
    const int tig   = lane & 3;

    const int m0 = blockIdx.y * TILE_M;
    const int n0 = blockIdx.x * TILE_N;

    const __half* xh = (const __half*)g_xh;
    const __half* wt = (const __half*)g_wt;

    float acc[2][8][4];
    #pragma unroll
    for (int i = 0; i < 2; i++)
        #pragma unroll
        for (int j = 0; j < 8; j++)
            #pragma unroll
            for (int c = 0; c < 4; c++) acc[i][j][c] = 0.f;

    // A ldmatrix lane mapping (in f16 elements)
    const int a_row = lane & 15;
    const int a_k   = (lane & 16) ? 8 : 0;
    const int a_base = (warp_m * 32 + a_row) * SSTR + a_k;
    // B ldmatrix.trans lane mapping: row = k (lane&15), col-offset = n
    const int b_k15  = lane & 15;
    const int b_noff = (lane & 16) ? 8 : 0;

    auto load_stage = [&](int s, int chunk) {
        const int k0 = chunk * TK;
        __half* st = sm + s * STAGE;
        // A: 128 rows x 32 k  (512 cp16; 2 per thread)
        #pragma unroll
        for (int r = 0; r < 2; r++) {
            int idx = tid + 256 * r;
            int row = idx >> 2;
            int c   = idx & 3;
            int gr  = m0 + row; if (gr >= N_NODES) gr = 0;
            cp16(st + row * SSTR + c * 8,
                 xh + (size_t)gr * IN_DIM + k0 + c * 8);
        }
        // B: 32 k-rows x 128 n  (512 cp16; 2 per thread), [k][n] layout
        #pragma unroll
        for (int r = 0; r < 2; r++) {
            int idx = tid + 256 * r;
            int row = idx >> 4;           // 0..31 (k)
            int c   = idx & 15;           // 16 chunks of 8 n
            cp16(st + OFF_B + row * SSTRB + c * 8,
                 wt + (size_t)(k0 + row) * HID + n0 + c * 8);
        }
    };

    load_stage(0, 0);
    asm volatile("cp.async.commit_group;" ::: "memory");

    for (int chunk = 0; chunk < NCHUNK; chunk++) {
        if (chunk + 1 < NCHUNK) load_stage((chunk + 1) & 1, chunk + 1);
        asm volatile("cp.async.commit_group;" ::: "memory");
        asm volatile("cp.async.wait_group 1;" ::: "memory");
        __syncthreads();

        const uint32_t stg = smaddr + (uint32_t)(chunk & 1) * (STAGE * 2);

        #pragma unroll
        for (int ks = 0; ks < 2; ks++) {
            const int kb = ks * 16;
            uint32_t a0[4], a1[4];
            uint32_t aa = stg + (uint32_t)(a_base + kb) * 2;
            ldsm_x4(a0, aa);
            ldsm_x4(a1, aa + 16 * SSTR * 2);
            #pragma unroll
            for (int p = 0; p < 4; p++) {
                uint32_t bh[4];
                uint32_t ba = stg + (uint32_t)(OFF_B + (kb + b_k15) * SSTRB
                                               + warp_n * 64 + p * 16 + b_noff) * 2;
                ldsm_x4_trans(bh, ba);
                mma_f16(acc[0][2 * p],     a0, bh[0], bh[1]);
                mma_f16(acc[1][2 * p],     a1, bh[0], bh[1]);
                mma_f16(acc[0][2 * p + 1], a0, bh[2], bh[3]);
                mma_f16(acc[1][2 * p + 1], a1, bh[2], bh[3]);
            }
        }
        __syncthreads();
    }

    // ---- epilogue: store hs as fp16 (half2 per acc pair) ------------------
    __half* hsh = (__half*)g_hsh;
    #pragma unroll
    for (int i = 0; i < 2; i++) {
        const int r0 = m0 + warp_m * 32 + i * 16 + quad;
        const int r1 = r0 + 8;
        const bool v0 = r0 < N_NODES;
        const bool v1 = r1 < N_NODES;
        #pragma unroll
        for (int j = 0; j < 8; j++) {
            const int col = n0 + warp_n * 64 + j * 8 + tig * 2;
            if (v0)
                *(uint32_t*)(hsh + (size_t)r0 * HID + col) = f2h2(acc[i][j][0], acc[i][j][1]);
            if (v1)
                *(uint32_t*)(hsh + (size_t)r1 * HID + col) = f2h2(acc[i][j][2], acc[i][j][3]);
        }
    }
}

// --- gather + relu + pool: one node per 64 threads, fp16 rows ---------------
__global__ __launch_bounds__(256) void gather_pool_kernel(
    const int* __restrict__ batch, const float* __restrict__ b)
{
    int t = blockIdx.x * blockDim.x + threadIdx.x;
    int n = t >> 6;
    int lane = t & 63;
    if (n >= N_NODES) return;

    int cnt = g_cnt[n];
    if (cnt > CSR_CAP) cnt = CSR_CAP;
    const int* lst = g_csr + n * CSR_CAP;

    auto addrow = [&](float4& a, uint2 raw) {
        __half2 p0, p1;
        memcpy(&p0, &raw.x, 4);
        memcpy(&p1, &raw.y, 4);
        float2 f0 = __half22float2(p0);
        float2 f1 = __half22float2(p1);
        a.x += f0.x; a.y += f0.y; a.z += f1.x; a.w += f1.y;
    };

    float4 a = make_float4(0.f, 0.f, 0.f, 0.f);
    addrow(a, __ldg(&g_hsh[(size_t)n * 64 + lane]));   // self loop

    int i = 0;
    for (; i + 8 <= cnt; i += 8) {
        int s[8];
        #pragma unroll
        for (int q = 0; q < 8; q++) s[q] = __ldg(&lst[i + q]);
        uint2 v[8];
        #pragma unroll
        for (int q = 0; q < 8; q++) v[q] = __ldg(&g_hsh[(size_t)s[q] * 64 + lane]);
        #pragma unroll
        for (int q = 0; q < 8; q++) addrow(a, v[q]);
    }
    for (; i < cnt; i++) {
        int s = __ldg(&lst[i]);
        addrow(a, __ldg(&g_hsh[(size_t)s * 64 + lane]));
    }

    float d = g_dinv[n];
    float4 bb = __ldg((const float4*)b + lane);
    float4 v;
    v.x = fmaxf(fmaf(a.x, d, bb.x), 0.f);
    v.y = fmaxf(fmaf(a.y, d, bb.y), 0.f);
    v.z = fmaxf(fmaf(a.z, d, bb.z), 0.f);
    v.w = fmaxf(fmaf(a.w, d, bb.w), 0.f);

    int g = __ldg(&batch[n]);
    red_add_v4(&g_pooled[(size_t)g * 64 + lane], v);
    if (lane == 0) atomicAdd(&g_counts[g], 1.f);
}

// --- head --------------------------------------------------------------------
__global__ void head_kernel(
    const float* __restrict__ lin_w, const float* __restrict__ lin_b,
    float* __restrict__ out)
{
    __shared__ float red[256];
    int g = blockIdx.x;
    int t = threadIdx.x;
    const float* pooled = (const float*)g_pooled;
    red[t] = pooled[g * HID + t] * __ldg(&lin_w[t]);
    __syncthreads();
    #pragma unroll
    for (int s = 128; s > 0; s >>= 1) {
        if (t < s) red[t] += red[t + s];
        __syncthreads();
    }
    if (t == 0) {
        float cnt = fmaxf(g_counts[g], 1.f);
        float z = red[0] / cnt + __ldg(&lin_b[0]);
        out[g] = 1.f / (1.f + expf(-z));
    }
}

// ---------------------------------------------------------------------------
extern "C" void kernel_launch(void* const* d_in, const int* in_sizes, int n_in,
                              void* d_out, int out_size) {
    const float* x     = (const float*)d_in[0];
    const int*   ei    = (const int*)d_in[1];
    const int*   batch = (const int*)d_in[2];
    const float* W     = (const float*)d_in[3];
    const float* b     = (const float*)d_in[4];
    const float* lin_w = (const float*)d_in[5];
    const float* lin_b = (const float*)d_in[6];
    float*       out   = (float*)d_out;

    static bool attr_set = false;
    if (!attr_set) {
        cudaFuncSetAttribute(gemm_mma_kernel,
                             cudaFuncAttributeMaxDynamicSharedMemorySize, SMEM_BYTES);
        attr_set = true;
    }

    init_kernel<<<(N_GRAPHS * HID + 255) / 256, 256>>>();
    edge_bin_kernel<<<(N_EDGES + 255) / 256, 256>>>(ei);
    dinv_kernel<<<(N_NODES + 255) / 256, 256>>>();
    convert_x_kernel<<<(N_NODES * IN_DIM / 4 + 1023) / 1024, 256>>>((const float4*)x);
    convert_w_kernel<<<(IN_DIM * HID / 4 + 255) / 256, 256>>>((const float4*)W);
    gemm_mma_kernel<<<dim3(HID / TILE_N, (N_NODES + TILE_M - 1) / TILE_M),
                      256, SMEM_BYTES>>>();
    gather_pool_kernel<<<(N_NODES * 64 + 255) / 256, 256>>>(batch, b);
    head_kernel<<<N_GRAPHS, 256>>>(lin_w, lin_b, out);
}